// round 3
// baseline (speedup 1.0000x reference)
#include <cuda_runtime.h>
#include <math.h>

// Problem constants
#define BB    64
#define FF    1024
#define HIDD  2048
#define NHH   4
#define HDD   512
#define KSS   4
#define EPSF  1e-6f
#define INV_SQRT_HD 0.04419417382415922f   // 1/sqrt(512)

// ---------------- scratch (__device__ globals: allocation-free) ----------------
__device__ float g_x[BB*HIDD];
__device__ float g_z[BB*HIDD];
__device__ float g_convact[BB*HIDD];
__device__ float g_q[BB*HIDD];
__device__ float g_k[BB*HIDD];   // unscaled k (for qkv gate dot); scaled on use
__device__ float g_v[BB*HIDD];
__device__ float g_fp[BB*NHH];
__device__ float g_ip[BB*NHH];
__device__ float g_emn[BB*NHH];  // exp(-m_new)
__device__ float g_nom[BB*HIDD]; // q^T @ C_new, per (b,h,e)
__device__ float g_den[BB*NHH];  // q^T @ n_new
__device__ float g_h[BB*HIDD];

// =====================================================================
// Skinny SGEMM: out[64 x N] += A[64 x K] * B[K x N]
// Tile: M=64, Ntile=32, Ktile=16; 256 threads, 4x2 microtile.
// Split-K across gridDim.y (epilogue atomicAdd; outputs zeroed beforehand).
// =====================================================================
__global__ void sgemm_m64(const float* __restrict__ A, const float* __restrict__ Bm,
                          int K, int N, int Kslice,
                          float* __restrict__ out0, float* __restrict__ out1, int split)
{
    __shared__ float As[16][64];
    __shared__ float Bs[16][32];
    int tid = threadIdx.x;              // 256
    int tm = tid >> 4, tn = tid & 15;   // 16x16 threads -> rows tm*4..+3, cols tn*2..+1
    float acc[4][2] = {};
    int nb = blockIdx.x * 32;
    int kbeg = blockIdx.y * Kslice;
    int kend = kbeg + Kslice;

    int la = tid * 4;  int am = la >> 4, ak = la & 15;   // A: 64x16 tile, float4 per thread
    int lb = tid * 2;  int bk = lb >> 5, bn = lb & 31;   // B: 16x32 tile, float2 per thread

    for (int k0 = kbeg; k0 < kend; k0 += 16) {
        float4 a4 = *(const float4*)(A + (size_t)am * K + k0 + ak);
        As[ak+0][am] = a4.x; As[ak+1][am] = a4.y; As[ak+2][am] = a4.z; As[ak+3][am] = a4.w;
        *(float2*)&Bs[bk][bn] = *(const float2*)(Bm + (size_t)(k0 + bk) * N + nb + bn);
        __syncthreads();
#pragma unroll
        for (int kk = 0; kk < 16; kk++) {
            float b0 = Bs[kk][tn*2+0];
            float b1 = Bs[kk][tn*2+1];
#pragma unroll
            for (int i = 0; i < 4; i++) {
                float a = As[kk][tm*4+i];
                acc[i][0] += a * b0;
                acc[i][1] += a * b1;
            }
        }
        __syncthreads();
    }
#pragma unroll
    for (int i = 0; i < 4; i++) {
#pragma unroll
        for (int j = 0; j < 2; j++) {
            int row = tm*4 + i;
            int col = nb + tn*2 + j;
            if (col < split) atomicAdd(&out0[row*split + col], acc[i][j]);
            else             atomicAdd(&out1[row*(N-split) + (col-split)], acc[i][j]);
        }
    }
}

// =====================================================================
// Per-batch prep: conv-state shift, causal conv + silu, block-diag q/k/v,
// gate dots (i_tilde/f_tilde), m_new / f_p / i_p / exp(-m_new).
// Also zeroes g_nom / g_den accumulators for this batch.
// One block per batch, 256 threads.
// =====================================================================
__global__ void prep_kernel(const float* __restrict__ conv_state,
                            const float* __restrict__ conv_w,
                            const float* __restrict__ conv_b,
                            const float* __restrict__ Wq,
                            const float* __restrict__ Wk,
                            const float* __restrict__ Wv,
                            const float* __restrict__ Wi,
                            const float* __restrict__ bi,
                            const float* __restrict__ Wf,
                            const float* __restrict__ bf,
                            const float* __restrict__ m_in,
                            float* __restrict__ out_cs,
                            float* __restrict__ out_m)
{
    __shared__ float s_x[HIDD];
    __shared__ float s_conv[HIDD];
    __shared__ float s_qkv[3*HIDD];
    __shared__ float s_red[64];   // 8 warps * 8 partials
    __shared__ float s_fin[8];

    int b = blockIdx.x;
    int tid = threadIdx.x;
    const float* cs  = conv_state + (size_t)b*KSS*HIDD;
    float*       ocs = out_cs     + (size_t)b*KSS*HIDD;

    // conv state shift, conv + silu
    for (int j = tid; j < HIDD; j += 256) {
        float xj = g_x[b*HIDD + j];
        s_x[j] = xj;
        float c1 = cs[1*HIDD + j], c2 = cs[2*HIDD + j], c3 = cs[3*HIDD + j];
        ocs[0*HIDD + j] = c1;
        ocs[1*HIDD + j] = c2;
        ocs[2*HIDD + j] = c3;
        ocs[3*HIDD + j] = xj;
        float conv = c1*conv_w[0*HIDD+j] + c2*conv_w[1*HIDD+j]
                   + c3*conv_w[2*HIDD+j] + xj*conv_w[3*HIDD+j] + conv_b[j];
        float act = conv / (1.f + expf(-conv));   // silu
        s_conv[j] = act;
        g_convact[b*HIDD + j] = act;
        g_nom[b*HIDD + j] = 0.f;                  // zero nom accumulator
    }
    if (tid < NHH) g_den[b*NHH + tid] = 0.f;
    __syncthreads();

    // block-diagonal q/k/v (4x4 blocks)
    for (int j = tid; j < HIDD; j += 256) {
        int nb4 = j >> 2, e = j & 3;
        const float* wq = Wq + nb4*16 + e;
        const float* wk = Wk + nb4*16 + e;
        const float* wv = Wv + nb4*16 + e;
        float a0 = s_conv[nb4*4+0], a1 = s_conv[nb4*4+1], a2 = s_conv[nb4*4+2], a3 = s_conv[nb4*4+3];
        float x0 = s_x[nb4*4+0],    x1 = s_x[nb4*4+1],    x2 = s_x[nb4*4+2],    x3 = s_x[nb4*4+3];
        float q = a0*wq[0] + a1*wq[4] + a2*wq[8] + a3*wq[12];
        float k = a0*wk[0] + a1*wk[4] + a2*wk[8] + a3*wk[12];
        float v = x0*wv[0] + x1*wv[4] + x2*wv[8] + x3*wv[12];
        s_qkv[j]          = q;
        s_qkv[HIDD + j]   = k;
        s_qkv[2*HIDD + j] = v;
        g_q[b*HIDD + j] = q;
        g_k[b*HIDD + j] = k;
        g_v[b*HIDD + j] = v;
    }
    __syncthreads();

    // gates: i_tilde/f_tilde = qkv @ Wi/Wf + bias (per head)
    float pi[NHH] = {0,0,0,0};
    float pf[NHH] = {0,0,0,0};
    const float4* Wi4 = (const float4*)Wi;
    const float4* Wf4 = (const float4*)Wf;
    for (int j = tid; j < 3*HIDD; j += 256) {
        float val = s_qkv[j];
        float4 wi = Wi4[j];
        float4 wf = Wf4[j];
        pi[0] += val*wi.x; pi[1] += val*wi.y; pi[2] += val*wi.z; pi[3] += val*wi.w;
        pf[0] += val*wf.x; pf[1] += val*wf.y; pf[2] += val*wf.z; pf[3] += val*wf.w;
    }
#pragma unroll
    for (int off = 16; off; off >>= 1) {
#pragma unroll
        for (int h = 0; h < NHH; h++) {
            pi[h] += __shfl_down_sync(0xffffffffu, pi[h], off);
            pf[h] += __shfl_down_sync(0xffffffffu, pf[h], off);
        }
    }
    int lane = tid & 31, warp = tid >> 5;
    if (lane == 0) {
#pragma unroll
        for (int h = 0; h < NHH; h++) {
            s_red[warp*8 + h]     = pi[h];
            s_red[warp*8 + 4 + h] = pf[h];
        }
    }
    __syncthreads();
    if (tid < 8) {
        float s = 0.f;
#pragma unroll
        for (int w = 0; w < 8; w++) s += s_red[w*8 + tid];
        s_fin[tid] = s;
    }
    __syncthreads();
    if (tid < NHH) {
        int h = tid;
        float it = s_fin[h]     + bi[h];
        float ft = s_fin[4 + h] + bf[h];
        // log_f = -softplus(-ft), numerically stable
        float logf = (ft > 0.f) ? -log1pf(expf(-ft)) : (ft - log1pf(expf(ft)));
        float mo = m_in[b*NHH + h];
        float mn = fmaxf(logf + mo, it);
        out_m[b*NHH + h] = mn;
        g_ip[b*NHH + h]  = expf(it - mn);
        g_fp[b*NHH + h]  = expf(logf + mo - mn);
        g_emn[b*NHH + h] = expf(-mn);
    }
}

// =====================================================================
// Fused C-state stream: C_new = f_p*C + i_p*(kh (x) v), plus
//   nom[e]  += sum_d q[d]*C_new[d,e]   (atomicAdd per column)
//   n_new[d] = f_p*n[d] + i_p*kh[d]
//   den     += sum_d q[d]*n_new[d]     (atomicAdd per bh)
// grid = (4 d-chunks of 128 rows, B*NH).  256 threads: 128 col-groups(x4) x 2 rows.
// Streaming cache hints: C has zero reuse.
// =====================================================================
__global__ void c_update_kernel(const float* __restrict__ C,
                                const float* __restrict__ n_in,
                                float* __restrict__ outC,
                                float* __restrict__ outN)
{
    int bh = blockIdx.y;
    int d0 = blockIdx.x * 128;
    int tid = threadIdx.x;  // 256

    __shared__ float s_kh[128];
    __shared__ float s_q[128];
    __shared__ float s_dp[8];

    float fp = g_fp[bh];
    float ip = g_ip[bh];

    if (tid < 128) {
        int d = d0 + tid;
        s_kh[tid] = g_k[bh*HDD + d] * INV_SQRT_HD;
        s_q[tid]  = g_q[bh*HDD + d];
    }
    __syncthreads();

    int tx = tid & 127;   // column group (4 cols each -> 512)
    int ty = tid >> 7;    // 0/1 row interleave
    float4 v4 = *(const float4*)(g_v + bh*HDD + tx*4);

    const float4* Cb = (const float4*)(C    + (size_t)bh*HDD*HDD);
    float4*       Ob = (float4*)      (outC + (size_t)bh*HDD*HDD);

    float4 acc = make_float4(0.f, 0.f, 0.f, 0.f);
#pragma unroll 4
    for (int dd = ty; dd < 128; dd += 2) {
        int d = d0 + dd;
        size_t idx = (size_t)d * (HDD/4) + tx;
        float4 c = __ldcs(Cb + idx);
        float ipk = ip * s_kh[dd];
        float4 cn;
        cn.x = fp*c.x + ipk*v4.x;
        cn.y = fp*c.y + ipk*v4.y;
        cn.z = fp*c.z + ipk*v4.z;
        cn.w = fp*c.w + ipk*v4.w;
        __stcs(Ob + idx, cn);
        float qd = s_q[dd];
        acc.x += qd*cn.x;
        acc.y += qd*cn.y;
        acc.z += qd*cn.z;
        acc.w += qd*cn.w;
    }
    float* nomp = g_nom + bh*HDD + tx*4;
    atomicAdd(nomp+0, acc.x);
    atomicAdd(nomp+1, acc.y);
    atomicAdd(nomp+2, acc.z);
    atomicAdd(nomp+3, acc.w);

    // n_new for the 128 rows this block owns + den partial
    float p = 0.f;
    if (tid < 128) {
        int d = d0 + tid;
        float nn = fp * n_in[bh*HDD + d] + ip * s_kh[tid];
        outN[bh*HDD + d] = nn;
        p = s_q[tid] * nn;
    }
#pragma unroll
    for (int off = 16; off; off >>= 1) p += __shfl_down_sync(0xffffffffu, p, off);
    int lane = tid & 31, warp = tid >> 5;
    if (lane == 0) s_dp[warp] = p;
    __syncthreads();
    if (tid == 0) {
        float s = 0.f;
#pragma unroll
        for (int w = 0; w < 8; w++) s += s_dp[w];
        atomicAdd(&g_den[bh], s);
    }
}

// =====================================================================
// Finalize per (b,h): h_tilde = nom/(den+eps), layernorm over HD,
// + skip*conv_act, * silu(z)  -> g_h.   grid=B*NH, 128 threads (x4 cols).
// =====================================================================
__global__ void finalize_kernel(const float* __restrict__ norm_scale,
                                const float* __restrict__ skip)
{
    int bh = blockIdx.x;
    int b = bh >> 2, h = bh & 3;
    int tid = threadIdx.x;  // 128

    __shared__ float ss[4], ss2[4];
    __shared__ float s_mean, s_rstd;

    float den = fmaxf(fabsf(g_den[bh]), g_emn[bh]) + EPSF;
    float inv = 1.f / den;

    float4 nom4 = *(const float4*)(g_nom + bh*HDD + tid*4);
    float4 ht;
    ht.x = nom4.x * inv; ht.y = nom4.y * inv; ht.z = nom4.z * inv; ht.w = nom4.w * inv;

    float s  = ht.x + ht.y + ht.z + ht.w;
    float s2 = ht.x*ht.x + ht.y*ht.y + ht.z*ht.z + ht.w*ht.w;
#pragma unroll
    for (int off = 16; off; off >>= 1) {
        s  += __shfl_down_sync(0xffffffffu, s,  off);
        s2 += __shfl_down_sync(0xffffffffu, s2, off);
    }
    int lane = tid & 31, warp = tid >> 5;
    if (lane == 0) { ss[warp] = s; ss2[warp] = s2; }
    __syncthreads();
    if (tid == 0) {
        float S  = ss[0] + ss[1] + ss[2] + ss[3];
        float S2 = ss2[0] + ss2[1] + ss2[2] + ss2[3];
        float mean = S / (float)HDD;
        float var  = S2 / (float)HDD - mean*mean;
        s_mean = mean;
        s_rstd = rsqrtf(var + EPSF);
    }
    __syncthreads();
    float mean = s_mean, rstd = s_rstd;

    const float* nsc = norm_scale + h*HDD + tid*4;
    int j0 = h*HDD + tid*4;
#pragma unroll
    for (int i = 0; i < 4; i++) {
        float htv = (i == 0) ? ht.x : (i == 1) ? ht.y : (i == 2) ? ht.z : ht.w;
        float hn = (htv - mean) * rstd * nsc[i];
        int j = j0 + i;
        float hh = hn + skip[j] * g_convact[b*HIDD + j];
        float z = g_z[b*HIDD + j];
        hh *= z / (1.f + expf(-z));
        g_h[b*HIDD + j] = hh;
    }
}

// =====================================================================
extern "C" void kernel_launch(void* const* d_in, const int* in_sizes, int n_in,
                              void* d_out, int out_size)
{
    const float* inputs     = (const float*)d_in[0];
    const float* C          = (const float*)d_in[1];
    const float* n_state    = (const float*)d_in[2];
    const float* m_state    = (const float*)d_in[3];
    const float* conv_state = (const float*)d_in[4];
    const float* W_up       = (const float*)d_in[5];
    const float* conv_w     = (const float*)d_in[6];
    const float* conv_b     = (const float*)d_in[7];
    const float* Wq         = (const float*)d_in[8];
    const float* Wk         = (const float*)d_in[9];
    const float* Wv         = (const float*)d_in[10];
    const float* Wi         = (const float*)d_in[11];
    const float* bi         = (const float*)d_in[12];
    const float* Wf         = (const float*)d_in[13];
    const float* bf         = (const float*)d_in[14];
    const float* norm_scale = (const float*)d_in[15];
    const float* skip       = (const float*)d_in[16];
    const float* W_down     = (const float*)d_in[17];

    float* out = (float*)d_out;
    // Output layout: y(64*1024) | C_new(64*4*512*512) | n_new(64*4*512) | m_new(256) | conv_state_new(64*4*2048)
    float* out_y  = out;
    float* out_C  = out_y + (size_t)BB*FF;                 // + 65536
    float* out_n  = out_C + (size_t)BB*NHH*HDD*HDD;        // + 67108864
    float* out_m  = out_n + (size_t)BB*NHH*HDD;            // + 131072
    float* out_cs = out_m + (size_t)BB*NHH;                // + 256

    float *px, *pz, *ph;
    cudaGetSymbolAddress((void**)&px, g_x);
    cudaGetSymbolAddress((void**)&pz, g_z);
    cudaGetSymbolAddress((void**)&ph, g_h);

    // zero split-K accumulation targets
    cudaMemsetAsync(px, 0, (size_t)BB*HIDD*sizeof(float));
    cudaMemsetAsync(pz, 0, (size_t)BB*HIDD*sizeof(float));
    cudaMemsetAsync(out_y, 0, (size_t)BB*FF*sizeof(float));

    // 1) up-projection: [64,1024] @ [1024,4096] -> x | z   (split-K=2)
    sgemm_m64<<<dim3((2*HIDD)/32, 2), 256>>>(inputs, W_up, FF, 2*HIDD, FF/2, px, pz, HIDD);

    // 2) conv / qkv / gates
    prep_kernel<<<BB, 256>>>(conv_state, conv_w, conv_b, Wq, Wk, Wv,
                             Wi, bi, Wf, bf, m_state, out_cs, out_m);

    // 3) fused C-state stream (the 537 MB)
    c_update_kernel<<<dim3(4, BB*NHH), 256>>>(C, n_state, out_C, out_n);

    // 4) h_tilde + layernorm + skip + z-gate
    finalize_kernel<<<BB*NHH, 128>>>(norm_scale, skip);

    // 5) down-projection: [64,2048] @ [2048,1024] -> y   (split-K=4)
    sgemm_m64<<<dim3(FF/32, 4), 256>>>(ph, W_down, HIDD, FF, HIDD/4, out_y, out_y, FF);
}

// round 5
// speedup vs baseline: 1.0726x; 1.0726x over previous
#include <cuda_runtime.h>
#include <math.h>

// Problem constants
#define BB    64
#define FF    1024
#define HIDD  2048
#define NHH   4
#define HDD   512
#define KSS   4
#define EPSF  1e-6f
#define INV_SQRT_HD 0.04419417382415922f   // 1/sqrt(512)

#define UP_SPLITK   4
#define DOWN_SPLITK 8
#define UPSZ   (BB*2*HIDD)          // 64*4096 elements per up partial slice
#define DNSZ   (BB*FF)              // 64*1024 elements per down partial slice

// ---------------- scratch (__device__ globals: allocation-free) ----------------
__device__ float g_up[UP_SPLITK*UPSZ];     // up-proj split-K partials (x|z)
__device__ float g_down[DOWN_SPLITK*DNSZ]; // down-proj split-K partials
__device__ float g_convact[BB*HIDD];
__device__ float g_q[BB*HIDD];
__device__ float g_k[BB*HIDD];
__device__ float g_v[BB*HIDD];
__device__ float g_fp[BB*NHH];
__device__ float g_ip[BB*NHH];
__device__ float g_emn[BB*NHH];  // exp(-m_new)
__device__ float g_nom[BB*HIDD]; // q^T @ C_new
__device__ float g_den[BB*NHH];  // q^T @ n_new
__device__ float g_h[BB*HIDD];

// =====================================================================
// Skinny SGEMM, split-K partials (no atomics): part[slice][64 x N]
// Tile 64 x 64 x 16, 256 threads, 4x4 microtile, float4 smem loads.
// Per kk: 2x LDS.128 + 16 FFMA  -> sits at both the smem (128B/cyc/SM)
// and FFMA (64/cyc/SM) roofs simultaneously.
// =====================================================================
__global__ void sgemm_m64_part(const float* __restrict__ A, const float* __restrict__ Bm,
                               int K, int N, int Kslice, float* __restrict__ part)
{
    __shared__ float As[16][64];
    __shared__ float Bs[16][64];
    int tid = threadIdx.x;              // 256
    int tm = tid >> 4, tn = tid & 15;   // 16x16 threads -> 4 rows x 4 cols each
    float acc[4][4] = {};
    int nb = blockIdx.x * 64;
    int kbeg = blockIdx.y * Kslice;
    int kend = kbeg + Kslice;

    int arow = tid & 63, ak4 = (tid >> 6) * 4;   // A: 64x16, conflict-free transpose store
    int brow = tid >> 4, bcol = (tid & 15) * 4;  // B: 16x64 float4

    for (int k0 = kbeg; k0 < kend; k0 += 16) {
        float4 a4 = *(const float4*)(A + (size_t)arow * K + k0 + ak4);
        As[ak4+0][arow] = a4.x; As[ak4+1][arow] = a4.y;
        As[ak4+2][arow] = a4.z; As[ak4+3][arow] = a4.w;
        *(float4*)&Bs[brow][bcol] = *(const float4*)(Bm + (size_t)(k0 + brow) * N + nb + bcol);
        __syncthreads();
#pragma unroll
        for (int kk = 0; kk < 16; kk++) {
            float4 a = *(const float4*)&As[kk][tm*4];
            float4 b = *(const float4*)&Bs[kk][tn*4];
            acc[0][0] += a.x*b.x; acc[0][1] += a.x*b.y; acc[0][2] += a.x*b.z; acc[0][3] += a.x*b.w;
            acc[1][0] += a.y*b.x; acc[1][1] += a.y*b.y; acc[1][2] += a.y*b.z; acc[1][3] += a.y*b.w;
            acc[2][0] += a.z*b.x; acc[2][1] += a.z*b.y; acc[2][2] += a.z*b.z; acc[2][3] += a.z*b.w;
            acc[3][0] += a.w*b.x; acc[3][1] += a.w*b.y; acc[3][2] += a.w*b.z; acc[3][3] += a.w*b.w;
        }
        __syncthreads();
    }
    float* dst = part + (size_t)blockIdx.y * 64 * N;
#pragma unroll
    for (int i = 0; i < 4; i++) {
        float4 v = make_float4(acc[i][0], acc[i][1], acc[i][2], acc[i][3]);
        *(float4*)(dst + (size_t)(tm*4 + i) * N + nb + tn*4) = v;
    }
}

// =====================================================================
// Per-batch prep: combine up-proj x-partials, conv-state shift,
// causal conv + silu, block-diag q/k/v, gate dots, m_new/f_p/i_p.
// Zeroes g_nom / g_den. One block per batch, 256 threads.
// =====================================================================
__global__ void prep_kernel(const float* __restrict__ conv_state,
                            const float* __restrict__ conv_w,
                            const float* __restrict__ conv_b,
                            const float* __restrict__ Wq,
                            const float* __restrict__ Wk,
                            const float* __restrict__ Wv,
                            const float* __restrict__ Wi,
                            const float* __restrict__ bi,
                            const float* __restrict__ Wf,
                            const float* __restrict__ bf,
                            const float* __restrict__ m_in,
                            float* __restrict__ out_cs,
                            float* __restrict__ out_m)
{
    __shared__ float s_x[HIDD];
    __shared__ float s_conv[HIDD];
    __shared__ float s_qkv[3*HIDD];
    __shared__ float s_red[64];
    __shared__ float s_fin[8];

    int b = blockIdx.x;
    int tid = threadIdx.x;
    const float* cs  = conv_state + (size_t)b*KSS*HIDD;
    float*       ocs = out_cs     + (size_t)b*KSS*HIDD;
    const float* up  = g_up + (size_t)b*(2*HIDD);

    for (int j = tid; j < HIDD; j += 256) {
        float xj = up[j] + up[UPSZ + j] + up[2*UPSZ + j] + up[3*UPSZ + j];
        s_x[j] = xj;
        float c1 = cs[1*HIDD + j], c2 = cs[2*HIDD + j], c3 = cs[3*HIDD + j];
        ocs[0*HIDD + j] = c1;
        ocs[1*HIDD + j] = c2;
        ocs[2*HIDD + j] = c3;
        ocs[3*HIDD + j] = xj;
        float conv = c1*conv_w[0*HIDD+j] + c2*conv_w[1*HIDD+j]
                   + c3*conv_w[2*HIDD+j] + xj*conv_w[3*HIDD+j] + conv_b[j];
        float act = conv / (1.f + expf(-conv));   // silu
        s_conv[j] = act;
        g_convact[b*HIDD + j] = act;
        g_nom[b*HIDD + j] = 0.f;
    }
    if (tid < NHH) g_den[b*NHH + tid] = 0.f;
    __syncthreads();

    // block-diagonal q/k/v (4x4 blocks)
    for (int j = tid; j < HIDD; j += 256) {
        int nb4 = j >> 2, e = j & 3;
        const float* wq = Wq + nb4*16 + e;
        const float* wk = Wk + nb4*16 + e;
        const float* wv = Wv + nb4*16 + e;
        float a0 = s_conv[nb4*4+0], a1 = s_conv[nb4*4+1], a2 = s_conv[nb4*4+2], a3 = s_conv[nb4*4+3];
        float x0 = s_x[nb4*4+0],    x1 = s_x[nb4*4+1],    x2 = s_x[nb4*4+2],    x3 = s_x[nb4*4+3];
        float q = a0*wq[0] + a1*wq[4] + a2*wq[8] + a3*wq[12];
        float k = a0*wk[0] + a1*wk[4] + a2*wk[8] + a3*wk[12];
        float v = x0*wv[0] + x1*wv[4] + x2*wv[8] + x3*wv[12];
        s_qkv[j]          = q;
        s_qkv[HIDD + j]   = k;
        s_qkv[2*HIDD + j] = v;
        g_q[b*HIDD + j] = q;
        g_k[b*HIDD + j] = k;
        g_v[b*HIDD + j] = v;
    }
    __syncthreads();

    // gates
    float pi[NHH] = {0,0,0,0};
    float pf[NHH] = {0,0,0,0};
    const float4* Wi4 = (const float4*)Wi;
    const float4* Wf4 = (const float4*)Wf;
    for (int j = tid; j < 3*HIDD; j += 256) {
        float val = s_qkv[j];
        float4 wi = Wi4[j];
        float4 wf = Wf4[j];
        pi[0] += val*wi.x; pi[1] += val*wi.y; pi[2] += val*wi.z; pi[3] += val*wi.w;
        pf[0] += val*wf.x; pf[1] += val*wf.y; pf[2] += val*wf.z; pf[3] += val*wf.w;
    }
#pragma unroll
    for (int off = 16; off; off >>= 1) {
#pragma unroll
        for (int h = 0; h < NHH; h++) {
            pi[h] += __shfl_down_sync(0xffffffffu, pi[h], off);
            pf[h] += __shfl_down_sync(0xffffffffu, pf[h], off);
        }
    }
    int lane = tid & 31, warp = tid >> 5;
    if (lane == 0) {
#pragma unroll
        for (int h = 0; h < NHH; h++) {
            s_red[warp*8 + h]     = pi[h];
            s_red[warp*8 + 4 + h] = pf[h];
        }
    }
    __syncthreads();
    if (tid < 8) {
        float s = 0.f;
#pragma unroll
        for (int w = 0; w < 8; w++) s += s_red[w*8 + tid];
        s_fin[tid] = s;
    }
    __syncthreads();
    if (tid < NHH) {
        int h = tid;
        float it = s_fin[h]     + bi[h];
        float ft = s_fin[4 + h] + bf[h];
        float logf = (ft > 0.f) ? -log1pf(expf(-ft)) : (ft - log1pf(expf(ft)));
        float mo = m_in[b*NHH + h];
        float mn = fmaxf(logf + mo, it);
        out_m[b*NHH + h] = mn;
        g_ip[b*NHH + h]  = expf(it - mn);
        g_fp[b*NHH + h]  = expf(logf + mo - mn);
        g_emn[b*NHH + h] = expf(-mn);
    }
}

// =====================================================================
// Fused C-state stream (the 537 MB). 64-row chunks for better wave
// balance: grid (8, B*NH) = 2048 blocks x 256 threads.
// =====================================================================
__global__ void c_update_kernel(const float* __restrict__ C,
                                const float* __restrict__ n_in,
                                float* __restrict__ outC,
                                float* __restrict__ outN)
{
    int bh = blockIdx.y;
    int d0 = blockIdx.x * 64;
    int tid = threadIdx.x;  // 256

    __shared__ float s_kh[64];
    __shared__ float s_q[64];

    float fp = g_fp[bh];
    float ip = g_ip[bh];

    if (tid < 64) {
        int d = d0 + tid;
        s_kh[tid] = g_k[bh*HDD + d] * INV_SQRT_HD;
        s_q[tid]  = g_q[bh*HDD + d];
    }
    __syncthreads();

    int tx = tid & 127;   // column group (x4 -> 512 cols)
    int ty = tid >> 7;    // row interleave
    float4 v4 = *(const float4*)(g_v + bh*HDD + tx*4);

    const float4* Cb = (const float4*)(C    + (size_t)bh*HDD*HDD);
    float4*       Ob = (float4*)      (outC + (size_t)bh*HDD*HDD);

    float4 acc = make_float4(0.f, 0.f, 0.f, 0.f);
#pragma unroll 8
    for (int dd = ty; dd < 64; dd += 2) {
        int d = d0 + dd;
        size_t idx = (size_t)d * (HDD/4) + tx;
        float4 c = __ldcs(Cb + idx);
        float ipk = ip * s_kh[dd];
        float4 cn;
        cn.x = fp*c.x + ipk*v4.x;
        cn.y = fp*c.y + ipk*v4.y;
        cn.z = fp*c.z + ipk*v4.z;
        cn.w = fp*c.w + ipk*v4.w;
        __stcs(Ob + idx, cn);
        float qd = s_q[dd];
        acc.x += qd*cn.x;
        acc.y += qd*cn.y;
        acc.z += qd*cn.z;
        acc.w += qd*cn.w;
    }
    float* nomp = g_nom + bh*HDD + tx*4;
    atomicAdd(nomp+0, acc.x);
    atomicAdd(nomp+1, acc.y);
    atomicAdd(nomp+2, acc.z);
    atomicAdd(nomp+3, acc.w);

    // n_new for the 64 rows this block owns + den partial
    if (tid < 64) {
        int d = d0 + tid;
        float nn = fp * n_in[bh*HDD + d] + ip * s_kh[tid];
        outN[bh*HDD + d] = nn;
        float p = s_q[tid] * nn;
#pragma unroll
        for (int off = 16; off; off >>= 1) p += __shfl_down_sync(0xffffffffu, p, off);
        if ((tid & 31) == 0) atomicAdd(&g_den[bh], p);
    }
}

// =====================================================================
// Finalize per (b,h): h_tilde = nom/(den+eps), layernorm over HD,
// + skip*conv_act, * silu(z) (z combined from up-partials) -> g_h.
// grid = B*NH, 128 threads.
// =====================================================================
__global__ void finalize_kernel(const float* __restrict__ norm_scale,
                                const float* __restrict__ skip)
{
    int bh = blockIdx.x;
    int b = bh >> 2, h = bh & 3;
    int tid = threadIdx.x;  // 128

    __shared__ float ss[4], ss2[4];
    __shared__ float s_mean, s_rstd;

    float den = fmaxf(fabsf(g_den[bh]), g_emn[bh]) + EPSF;
    float inv = 1.f / den;

    float4 nom4 = *(const float4*)(g_nom + bh*HDD + tid*4);
    float4 ht;
    ht.x = nom4.x * inv; ht.y = nom4.y * inv; ht.z = nom4.z * inv; ht.w = nom4.w * inv;

    float s  = ht.x + ht.y + ht.z + ht.w;
    float s2 = ht.x*ht.x + ht.y*ht.y + ht.z*ht.z + ht.w*ht.w;
#pragma unroll
    for (int off = 16; off; off >>= 1) {
        s  += __shfl_down_sync(0xffffffffu, s,  off);
        s2 += __shfl_down_sync(0xffffffffu, s2, off);
    }
    int lane = tid & 31, warp = tid >> 5;
    if (lane == 0) { ss[warp] = s; ss2[warp] = s2; }
    __syncthreads();
    if (tid == 0) {
        float S  = ss[0] + ss[1] + ss[2] + ss[3];
        float S2 = ss2[0] + ss2[1] + ss2[2] + ss2[3];
        float mean = S / (float)HDD;
        float var  = S2 / (float)HDD - mean*mean;
        s_mean = mean;
        s_rstd = rsqrtf(var + EPSF);
    }
    __syncthreads();
    float mean = s_mean, rstd = s_rstd;

    // z = sum of up-proj partials, columns [HID + h*HD + tid*4 ...]
    const float4* z0 = (const float4*)(g_up + 0*UPSZ + (size_t)b*(2*HIDD) + HIDD + h*HDD);
    const float4* z1 = (const float4*)(g_up + 1*UPSZ + (size_t)b*(2*HIDD) + HIDD + h*HDD);
    const float4* z2 = (const float4*)(g_up + 2*UPSZ + (size_t)b*(2*HIDD) + HIDD + h*HDD);
    const float4* z3 = (const float4*)(g_up + 3*UPSZ + (size_t)b*(2*HIDD) + HIDD + h*HDD);
    float4 za = z0[tid], zb = z1[tid], zc = z2[tid], zd = z3[tid];
    float zv[4];
    zv[0] = za.x + zb.x + zc.x + zd.x;
    zv[1] = za.y + zb.y + zc.y + zd.y;
    zv[2] = za.z + zb.z + zc.z + zd.z;
    zv[3] = za.w + zb.w + zc.w + zd.w;

    const float* nsc = norm_scale + h*HDD + tid*4;
    int j0 = h*HDD + tid*4;
#pragma unroll
    for (int i = 0; i < 4; i++) {
        float htv = (i == 0) ? ht.x : (i == 1) ? ht.y : (i == 2) ? ht.z : ht.w;
        float hn = (htv - mean) * rstd * nsc[i];
        int j = j0 + i;
        float hh = hn + skip[j] * g_convact[b*HIDD + j];
        float z = zv[i];
        hh *= z / (1.f + expf(-z));
        g_h[b*HIDD + j] = hh;
    }
}

// =====================================================================
// y = sum of down-proj split-K partials. 16384 float4s.
// =====================================================================
__global__ void combine_y_kernel(float* __restrict__ out_y)
{
    int i = blockIdx.x * 256 + threadIdx.x;   // over 16384 float4
    const float4* d = (const float4*)g_down;
    float4 s = make_float4(0.f, 0.f, 0.f, 0.f);
#pragma unroll
    for (int k = 0; k < DOWN_SPLITK; k++) {
        float4 v = d[(size_t)k * (DNSZ/4) + i];
        s.x += v.x; s.y += v.y; s.z += v.z; s.w += v.w;
    }
    ((float4*)out_y)[i] = s;
}

// =====================================================================
extern "C" void kernel_launch(void* const* d_in, const int* in_sizes, int n_in,
                              void* d_out, int out_size)
{
    const float* inputs     = (const float*)d_in[0];
    const float* C          = (const float*)d_in[1];
    const float* n_state    = (const float*)d_in[2];
    const float* m_state    = (const float*)d_in[3];
    const float* conv_state = (const float*)d_in[4];
    const float* W_up       = (const float*)d_in[5];
    const float* conv_w     = (const float*)d_in[6];
    const float* conv_b     = (const float*)d_in[7];
    const float* Wq         = (const float*)d_in[8];
    const float* Wk         = (const float*)d_in[9];
    const float* Wv         = (const float*)d_in[10];
    const float* Wi         = (const float*)d_in[11];
    const float* bi         = (const float*)d_in[12];
    const float* Wf         = (const float*)d_in[13];
    const float* bf         = (const float*)d_in[14];
    const float* norm_scale = (const float*)d_in[15];
    const float* skip       = (const float*)d_in[16];
    const float* W_down     = (const float*)d_in[17];

    float* out = (float*)d_out;
    // Output layout: y(64*1024) | C_new(64*4*512*512) | n_new(64*4*512) | m_new(256) | conv_state_new(64*4*2048)
    float* out_y  = out;
    float* out_C  = out_y + (size_t)BB*FF;
    float* out_n  = out_C + (size_t)BB*NHH*HDD*HDD;
    float* out_m  = out_n + (size_t)BB*NHH*HDD;
    float* out_cs = out_m + (size_t)BB*NHH;

    float *pup, *pdown, *ph;
    cudaGetSymbolAddress((void**)&pup, g_up);
    cudaGetSymbolAddress((void**)&pdown, g_down);
    cudaGetSymbolAddress((void**)&ph, g_h);

    // 1) up-projection: [64,1024] @ [1024,4096] -> partials (split-K=4)
    sgemm_m64_part<<<dim3((2*HIDD)/64, UP_SPLITK), 256>>>(inputs, W_up, FF, 2*HIDD,
                                                          FF/UP_SPLITK, pup);

    // 2) conv / qkv / gates (combines x-partials)
    prep_kernel<<<BB, 256>>>(conv_state, conv_w, conv_b, Wq, Wk, Wv,
                             Wi, bi, Wf, bf, m_state, out_cs, out_m);

    // 3) fused C-state stream (the 537 MB)
    c_update_kernel<<<dim3(8, BB*NHH), 256>>>(C, n_state, out_C, out_n);

    // 4) h_tilde + layernorm + skip + z-gate (combines z-partials)
    finalize_kernel<<<BB*NHH, 128>>>(norm_scale, skip);

    // 5) down-projection: [64,2048] @ [2048,1024] -> partials (split-K=8)
    sgemm_m64_part<<<dim3(FF/64, DOWN_SPLITK), 256>>>(ph, W_down, HIDD, FF,
                                                      HIDD/DOWN_SPLITK, pdown);

    // 6) combine y partials
    combine_y_kernel<<<(BB*FF/4)/256, 256>>>(out_y);
}